// round 10
// baseline (speedup 1.0000x reference)
#include <cuda_runtime.h>
#include <math.h>

#define B_  32
#define S_  50
#define Q_  75
#define T_  128
#define F_  64
#define D_  256
#define KW  5
#define NS  (B_*S_)          // 1600 support samples
#define NQ  (B_*Q_)          // 2400 query samples
#define SUPB (NS/8)          // 200 support blocks (8 samples each)
#define QB   (NQ/8)          // 300 query blocks

// Scratch (device globals: allocation-free per harness rules)
__device__ float g_spooled[NS * F_];     // pooled support (400 KB)
__device__ float g_qfeat[NQ * F_];       // pooled queries (600 KB)
__device__ float g_G[F_ * F_];           // Gram G = W W^T, row-major (16 KB)
__device__ float g_a[NQ];                // a_q = q G q^T

// ---------------------------------------------------------------------------
// K1: Gram G = W W^T (64x64). Block i computes row i; warp w computes
// j = w*8..w*8+7 via lane-partitioned dots. No __syncthreads.
// ---------------------------------------------------------------------------
__global__ void __launch_bounds__(256) gram_kernel(const float* __restrict__ Wm) {
    int i    = blockIdx.x;
    int warp = threadIdx.x >> 5;
    int lane = threadIdx.x & 31;

    float wi[8];
    #pragma unroll
    for (int u = 0; u < 8; u++)
        wi[u] = Wm[i * D_ + lane + 32 * u];

    #pragma unroll
    for (int jj = 0; jj < 8; jj++) {
        int j = warp * 8 + jj;
        const float* wj = Wm + j * D_;
        float s = 0.f;
        #pragma unroll
        for (int u = 0; u < 8; u++)
            s += wi[u] * wj[lane + 32 * u];
        #pragma unroll
        for (int off = 16; off > 0; off >>= 1)
            s += __shfl_xor_sync(0xffffffffu, s, off);
        if (lane == 0) g_G[i * F_ + j] = s;
    }
}

// ---------------------------------------------------------------------------
// K2: mean-pool, warp-per-sample (8 samples/block, 500 blocks).
// lane = f4 (0..15) x tg (0..1); thread sums 64 float4 (t = tg + 2i):
// each warp-iteration reads 512B contiguous. One shfl_xor(16) combine.
// Query blocks additionally compute a = q G q^T (G staged in smem; the
// 128 FMA/thread hide under the DRAM-bound pooling).
// ---------------------------------------------------------------------------
__global__ void __launch_bounds__(256) pool_kernel(const float* __restrict__ sx,
                                                   const float* __restrict__ qx) {
    __shared__ float Gs[F_ * F_];    // 16 KB (query blocks only)
    __shared__ float qsm[8][F_];     // 2 KB

    int tid  = threadIdx.x;
    int lane = tid & 31;
    int warp = tid >> 5;
    int f4   = lane & 15;
    int tg   = lane >> 4;
    bool isq = blockIdx.x >= SUPB;

    // Stage G early (overlaps with the pooling DRAM loads below)
    if (isq) {
        const float4* gsrc = reinterpret_cast<const float4*>(g_G);
        float4* gdst = reinterpret_cast<float4*>(Gs);
        #pragma unroll
        for (int u = 0; u < 4; u++) gdst[tid + 256 * u] = gsrc[tid + 256 * u];
    }

    int sn = (isq ? (blockIdx.x - SUPB) : blockIdx.x) * 8 + warp;
    const float4* src = (isq ? reinterpret_cast<const float4*>(qx)
                             : reinterpret_cast<const float4*>(sx))
                        + (size_t)sn * (T_ * F_ / 4);

    float4 a0 = make_float4(0.f,0.f,0.f,0.f);
    float4 a1 = make_float4(0.f,0.f,0.f,0.f);
    #pragma unroll 8
    for (int i = 0; i < 64; i += 2) {
        float4 v0 = src[(tg + 2 * i) * 16 + f4];
        float4 v1 = src[(tg + 2 * (i + 1)) * 16 + f4];
        a0.x += v0.x; a0.y += v0.y; a0.z += v0.z; a0.w += v0.w;
        a1.x += v1.x; a1.y += v1.y; a1.z += v1.z; a1.w += v1.w;
    }

    const float inv = 1.0f / (float)T_;
    float4 r;
    r.x = a0.x + a1.x; r.y = a0.y + a1.y; r.z = a0.z + a1.z; r.w = a0.w + a1.w;
    r.x += __shfl_xor_sync(0xffffffffu, r.x, 16);
    r.y += __shfl_xor_sync(0xffffffffu, r.y, 16);
    r.z += __shfl_xor_sync(0xffffffffu, r.z, 16);
    r.w += __shfl_xor_sync(0xffffffffu, r.w, 16);
    r.x *= inv; r.y *= inv; r.z *= inv; r.w *= inv;

    float4* dst = (isq ? reinterpret_cast<float4*>(g_qfeat)
                       : reinterpret_cast<float4*>(g_spooled)) + sn * 16;
    if (tg == 0) dst[f4] = r;

    if (isq) {
        if (tg == 0) reinterpret_cast<float4*>(qsm)[warp * 16 + f4] = r;
        __syncthreads();

        // e_j = sum_i G[i][j] q_i for j = lane, lane+32; then a = q . e
        float e0 = 0.f, e1 = 0.f;
        const float* qrow = qsm[warp];
        #pragma unroll
        for (int i = 0; i < F_; i++) {
            float qi = qrow[i];
            e0 = fmaf(Gs[i * F_ + lane],      qi, e0);
            e1 = fmaf(Gs[i * F_ + lane + 32], qi, e1);
        }
        float aa = qrow[lane] * e0 + qrow[lane + 32] * e1;
        #pragma unroll
        for (int off = 16; off > 0; off >>= 1)
            aa += __shfl_xor_sync(0xffffffffu, aa, off);
        if (lane == 0) g_a[sn] = aa;
    }
}

// ---------------------------------------------------------------------------
// K3: per-episode proto + h_k = G p_k + c_k = p_k.h_k + all 75 query logits.
// One block per episode, 256 threads. Distance phase per warp-query:
// 2 LDG for q, scalar a, five 64-dim dots vs smem h. No G here.
// ---------------------------------------------------------------------------
__global__ void __launch_bounds__(256) protodist_kernel(const int* __restrict__ y,
                                                        float* __restrict__ out) {
    int b    = blockIdx.x;
    int tid  = threadIdx.x;
    int lane = tid & 31;
    int warp = tid >> 5;

    __shared__ int   ys[S_];
    __shared__ float psh[KW][F_];
    __shared__ float hsh[KW][F_];
    __shared__ float csh[KW];

    if (tid < S_) ys[tid] = y[b * S_ + tid];
    __syncthreads();

    if (tid < F_) {
        int f = tid;
        float a0=0.f,a1=0.f,a2=0.f,a3=0.f,a4=0.f;
        int   c0=0,c1=0,c2=0,c3=0,c4=0;
        #pragma unroll 10
        for (int s = 0; s < S_; s++) {
            float v = g_spooled[(b * S_ + s) * F_ + f];
            int l = ys[s];
            if (l == 0) { a0 += v; c0++; }
            if (l == 1) { a1 += v; c1++; }
            if (l == 2) { a2 += v; c2++; }
            if (l == 3) { a3 += v; c3++; }
            if (l == 4) { a4 += v; c4++; }
        }
        psh[0][f] = c0 ? a0 / (float)c0 : 0.f;
        psh[1][f] = c1 ? a1 / (float)c1 : 0.f;
        psh[2][f] = c2 ? a2 / (float)c2 : 0.f;
        psh[3][f] = c3 ? a3 / (float)c3 : 0.f;
        psh[4][f] = c4 ? a4 / (float)c4 : 0.f;
    }
    __syncthreads();

    if (tid < F_) {
        int f = tid;
        float hk[KW];
        #pragma unroll
        for (int k = 0; k < KW; k++) hk[k] = 0.f;
        for (int i = 0; i < F_; i++) {
            float gi = g_G[i * F_ + f];
            #pragma unroll
            for (int k = 0; k < KW; k++)
                hk[k] = fmaf(gi, psh[k][i], hk[k]);
        }
        #pragma unroll
        for (int k = 0; k < KW; k++) hsh[k][f] = hk[k];
    }
    __syncthreads();

    if (tid < 32) {
        #pragma unroll
        for (int k = 0; k < KW; k++) {
            float v = hsh[k][tid] * psh[k][tid] + hsh[k][tid + 32] * psh[k][tid + 32];
            #pragma unroll
            for (int off = 16; off > 0; off >>= 1)
                v += __shfl_xor_sync(0xffffffffu, v, off);
            if (tid == 0) csh[k] = v;
        }
    }
    __syncthreads();

    for (int r = 0; r < 10; r++) {
        int q = r * 8 + warp;
        if (q >= Q_) break;
        int bq = b * Q_ + q;
        float q0 = g_qfeat[bq * F_ + lane];
        float q1 = g_qfeat[bq * F_ + lane + 32];
        float aa = g_a[bq];
        #pragma unroll
        for (int k = 0; k < KW; k++) {
            float s = q0 * hsh[k][lane] + q1 * hsh[k][lane + 32];
            #pragma unroll
            for (int off = 16; off > 0; off >>= 1)
                s += __shfl_xor_sync(0xffffffffu, s, off);
            if (lane == 0)
                out[bq * KW + k] = -sqrtf(fmaxf(aa - 2.f * s + csh[k], 0.f));
        }
    }
}

// ---------------------------------------------------------------------------
// Inputs (metadata order): support_x f32, support_y i32, query_x f32, W f32, b f32
// Output: f32 [B*Q, KW] = [2400, 5]
// ---------------------------------------------------------------------------
extern "C" void kernel_launch(void* const* d_in, const int* in_sizes, int n_in,
                              void* d_out, int out_size) {
    const float* sx = (const float*)d_in[0];
    const int*   sy = (const int*)  d_in[1];
    const float* qx = (const float*)d_in[2];
    const float* Wm = (const float*)d_in[3];
    float* out = (float*)d_out;

    gram_kernel     <<<F_,        256>>>(Wm);   // G before pool (pool consumes it)
    pool_kernel     <<<SUPB + QB, 256>>>(sx, qx);
    protodist_kernel<<<B_,        256>>>(sy, out);
}

// round 11
// speedup vs baseline: 1.1189x; 1.1189x over previous
#include <cuda_runtime.h>
#include <math.h>

#define B_  32
#define S_  50
#define Q_  75
#define T_  128
#define F_  64
#define D_  256
#define KW  5
#define NS  (B_*S_)          // 1600 support samples
#define NQ  (B_*Q_)          // 2400 query samples
#define NTOT (NS+NQ)         // 4000
#define POOLB (NTOT/16)      // 250 pool blocks (16 samples each)

// Scratch (device globals: allocation-free per harness rules)
__device__ float g_spooled[NS * F_];     // pooled support (400 KB)
__device__ float g_qfeat[NQ * F_];       // pooled queries (600 KB)
__device__ float g_G[F_ * F_];           // Gram G = W W^T (16 KB, L2-resident)
__device__ float g_h[B_ * KW * F_];      // h_k = G p_k
__device__ float g_c[B_ * KW];           // c_k = p_k . h_k

// ---------------------------------------------------------------------------
// K1: pool + gram in ONE launch.
//  blocks [0, POOLB): mean-pool, sync-free, 16 samples/block (proven R5 path).
//  blocks [POOLB, POOLB+64): Gram row i = bid-POOLB. Latency-bound gram work
//  overlaps the DRAM-bound pool; no intra-grid dependency (G consumed later).
// ---------------------------------------------------------------------------
__global__ void __launch_bounds__(256) poolgram_kernel(const float* __restrict__ sx,
                                                       const float* __restrict__ qx,
                                                       const float* __restrict__ Wm) {
    int tid = threadIdx.x;

    if (blockIdx.x < POOLB) {
        // ---- pool: thread = (sample = tid>>4, f4 = tid&15), private T-sum ----
        int f4  = tid & 15;
        int sn  = blockIdx.x * 16 + (tid >> 4);

        const float4* src;
        float4* dst;
        if (sn < NS) {
            src = reinterpret_cast<const float4*>(sx) + (size_t)sn * (T_ * F_ / 4);
            dst = reinterpret_cast<float4*>(g_spooled) + sn * 16 + f4;
        } else {
            src = reinterpret_cast<const float4*>(qx) + (size_t)(sn - NS) * (T_ * F_ / 4);
            dst = reinterpret_cast<float4*>(g_qfeat) + (sn - NS) * 16 + f4;
        }

        float4 a0 = make_float4(0.f,0.f,0.f,0.f);
        float4 a1 = make_float4(0.f,0.f,0.f,0.f);
        #pragma unroll 8
        for (int t = 0; t < T_; t += 2) {
            float4 v0 = src[t * 16 + f4];
            float4 v1 = src[(t + 1) * 16 + f4];
            a0.x += v0.x; a0.y += v0.y; a0.z += v0.z; a0.w += v0.w;
            a1.x += v1.x; a1.y += v1.y; a1.z += v1.z; a1.w += v1.w;
        }
        const float inv = 1.0f / (float)T_;
        float4 r;
        r.x = (a0.x + a1.x) * inv;
        r.y = (a0.y + a1.y) * inv;
        r.z = (a0.z + a1.z) * inv;
        r.w = (a0.w + a1.w) * inv;
        *dst = r;
    } else {
        // ---- gram: block computes G row i; warp w owns j = w*8..w*8+7 ----
        // 64 independent LDGs in flight per warp (MLP), reduces at the end.
        int i    = blockIdx.x - POOLB;
        int warp = tid >> 5;
        int lane = tid & 31;

        float wi[8];
        #pragma unroll
        for (int u = 0; u < 8; u++)
            wi[u] = Wm[i * D_ + lane + 32 * u];

        float s[8];
        #pragma unroll
        for (int jj = 0; jj < 8; jj++) s[jj] = 0.f;

        #pragma unroll
        for (int u = 0; u < 8; u++) {
            #pragma unroll
            for (int jj = 0; jj < 8; jj++)
                s[jj] = fmaf(wi[u], Wm[(warp * 8 + jj) * D_ + lane + 32 * u], s[jj]);
        }

        #pragma unroll
        for (int jj = 0; jj < 8; jj++) {
            #pragma unroll
            for (int off = 16; off > 0; off >>= 1)
                s[jj] += __shfl_xor_sync(0xffffffffu, s[jj], off);
        }
        if (lane == 0) {
            #pragma unroll
            for (int jj = 0; jj < 8; jj++)
                g_G[i * F_ + warp * 8 + jj] = s[jj];
        }
    }
}

// ---------------------------------------------------------------------------
// K2: per-episode prototypes + h_k = G p_k + c_k = p_k.h_k.
// One block per episode, 64 threads (thread = feature f).
// ---------------------------------------------------------------------------
__global__ void __launch_bounds__(64) proto_kernel(const int* __restrict__ y) {
    int b = blockIdx.x;
    int f = threadIdx.x;

    __shared__ int   ys[S_];
    __shared__ float psh[KW][F_];
    __shared__ float csh[KW][F_];

    if (f < S_) ys[f] = y[b * S_ + f];
    __syncthreads();

    float a0=0.f,a1=0.f,a2=0.f,a3=0.f,a4=0.f;
    int   c0=0,c1=0,c2=0,c3=0,c4=0;
    #pragma unroll 10
    for (int s = 0; s < S_; s++) {
        float v = g_spooled[(b * S_ + s) * F_ + f];
        int l = ys[s];
        if (l == 0) { a0 += v; c0++; }
        if (l == 1) { a1 += v; c1++; }
        if (l == 2) { a2 += v; c2++; }
        if (l == 3) { a3 += v; c3++; }
        if (l == 4) { a4 += v; c4++; }
    }
    psh[0][f] = c0 ? a0 / (float)c0 : 0.f;
    psh[1][f] = c1 ? a1 / (float)c1 : 0.f;
    psh[2][f] = c2 ? a2 / (float)c2 : 0.f;
    psh[3][f] = c3 ? a3 / (float)c3 : 0.f;
    psh[4][f] = c4 ? a4 / (float)c4 : 0.f;
    __syncthreads();

    // h[k][f] = sum_i G[i][f] * p[k][i]  (G symmetric -> coalesced reads)
    float hk[KW];
    #pragma unroll
    for (int k = 0; k < KW; k++) hk[k] = 0.f;
    for (int i = 0; i < F_; i++) {
        float gi = g_G[i * F_ + f];
        #pragma unroll
        for (int k = 0; k < KW; k++)
            hk[k] = fmaf(gi, psh[k][i], hk[k]);
    }
    #pragma unroll
    for (int k = 0; k < KW; k++) {
        g_h[(b * KW + k) * F_ + f] = hk[k];
        csh[k][f] = psh[k][f] * hk[k];
    }
    __syncthreads();

    if (f < 32) {
        #pragma unroll
        for (int k = 0; k < KW; k++) {
            float v = csh[k][f] + csh[k][f + 32];
            #pragma unroll
            for (int off = 16; off > 0; off >>= 1)
                v += __shfl_xor_sync(0xffffffffu, v, off);
            if (f == 0) g_c[b * KW + k] = v;
        }
    }
}

// ---------------------------------------------------------------------------
// K3: logits. 300 blocks, warp-per-query (bq = bid*8 + warp, exact 2400).
// Per warp: a = q G q^T with G read straight from L2 (hot 16 KB, coalesced,
// fully unrolled -> deep MLP; NO smem staging, NO occupancy cliff), then
// five 64-dim dots against h_k from L2. Handles episode straddling per-warp.
// ---------------------------------------------------------------------------
__global__ void __launch_bounds__(256) dist_kernel(float* __restrict__ out) {
    int tid  = threadIdx.x;
    int warp = tid >> 5;
    int lane = tid & 31;
    int bq   = blockIdx.x * 8 + warp;     // 300*8 = 2400 = NQ exactly
    int b    = bq / Q_;

    __shared__ float qsh[8][F_];

    float q0 = g_qfeat[bq * F_ + lane];
    float q1 = g_qfeat[bq * F_ + lane + 32];
    qsh[warp][lane]      = q0;
    qsh[warp][lane + 32] = q1;
    __syncwarp();

    // e = G q ; lane owns columns lane and lane+32
    float e0 = 0.f, e1 = 0.f;
    #pragma unroll
    for (int i = 0; i < F_; i++) {
        float qi = qsh[warp][i];
        e0 = fmaf(g_G[i * F_ + lane],      qi, e0);
        e1 = fmaf(g_G[i * F_ + lane + 32], qi, e1);
    }
    float a = q0 * e0 + q1 * e1;
    #pragma unroll
    for (int off = 16; off > 0; off >>= 1)
        a += __shfl_xor_sync(0xffffffffu, a, off);

    #pragma unroll
    for (int k = 0; k < KW; k++) {
        const float* hk = g_h + (b * KW + k) * F_;
        float s = q0 * hk[lane] + q1 * hk[lane + 32];
        #pragma unroll
        for (int off = 16; off > 0; off >>= 1)
            s += __shfl_xor_sync(0xffffffffu, s, off);
        if (lane == 0)
            out[bq * KW + k] = -sqrtf(fmaxf(a - 2.f * s + g_c[b * KW + k], 0.f));
    }
}

// ---------------------------------------------------------------------------
// Inputs (metadata order): support_x f32, support_y i32, query_x f32, W f32, b f32
// Output: f32 [B*Q, KW] = [2400, 5]
// ---------------------------------------------------------------------------
extern "C" void kernel_launch(void* const* d_in, const int* in_sizes, int n_in,
                              void* d_out, int out_size) {
    const float* sx = (const float*)d_in[0];
    const int*   sy = (const int*)  d_in[1];
    const float* qx = (const float*)d_in[2];
    const float* Wm = (const float*)d_in[3];
    float* out = (float*)d_out;

    poolgram_kernel<<<POOLB + F_, 256>>>(sx, qx, Wm);
    proto_kernel   <<<B_,          64>>>(sy);
    dist_kernel    <<<NQ / 8,     256>>>(out);
}

// round 12
// speedup vs baseline: 1.2619x; 1.1278x over previous
#include <cuda_runtime.h>
#include <math.h>

#define B_  32
#define S_  50
#define Q_  75
#define T_  128
#define F_  64
#define D_  256
#define KW  5
#define NS  (B_*S_)          // 1600 support samples
#define NQ  (B_*Q_)          // 2400 query samples
#define NTOT (NS+NQ)         // 4000
#define POOLB (NTOT/4)       // 1000 pool blocks (4 samples each, 64 thr/sample)

// Scratch (device globals: allocation-free per harness rules)
__device__ float g_spooled[NS * F_];     // pooled support (400 KB)
__device__ float g_qfeat[NQ * F_];       // pooled queries (600 KB)
__device__ float g_G[F_ * F_];           // Gram G = W W^T (16 KB, L2-resident)
__device__ float g_h[B_ * KW * F_];      // h_k = G p_k
__device__ float g_c[B_ * KW];           // c_k = p_k . h_k

// ---------------------------------------------------------------------------
// K1: pool + gram in ONE launch.
//  blocks [0, POOLB): mean-pool with T split 4-ways per (sample,f4):
//    thread = (s_local = tid>>6, warp_in_sample = (tid>>5)&1, th = lane>>4,
//              f4 = lane&15); each thread sums 32 float4 (t = wis*64+th+2i).
//    4x the threads of the old layout -> occ 21% -> ~84%, the measured
//    bottleneck (DRAM stuck at 52% from too few bytes in flight).
//  blocks [POOLB, POOLB+64): Gram row i (latency-bound, hides under pool).
// ---------------------------------------------------------------------------
__global__ void __launch_bounds__(256) poolgram_kernel(const float* __restrict__ sx,
                                                       const float* __restrict__ qx,
                                                       const float* __restrict__ Wm) {
    int tid = threadIdx.x;

    if (blockIdx.x < POOLB) {
        int lane    = tid & 31;
        int s_local = tid >> 6;          // 0..3
        int wis     = (tid >> 5) & 1;    // warp-in-sample: 0..1
        int th      = lane >> 4;         // 0..1
        int f4      = lane & 15;         // 0..15

        int sn = blockIdx.x * 4 + s_local;
        const float4* src;
        float4* dstbase;
        if (sn < NS) {
            src     = reinterpret_cast<const float4*>(sx) + (size_t)sn * (T_ * F_ / 4);
            dstbase = reinterpret_cast<float4*>(g_spooled);
        } else {
            src     = reinterpret_cast<const float4*>(qx) + (size_t)(sn - NS) * (T_ * F_ / 4);
            dstbase = reinterpret_cast<float4*>(g_qfeat) - (size_t)NS * 16;
        }

        // t = wis*64 + th + 2*i, i = 0..31. Warp iteration reads 512B contig.
        const float4* p = src + (wis * 64 + th) * 16 + f4;
        float4 a0 = make_float4(0.f,0.f,0.f,0.f);
        float4 a1 = make_float4(0.f,0.f,0.f,0.f);
        #pragma unroll 4
        for (int i = 0; i < 32; i += 2) {
            float4 v0 = p[(2 * i) * 16];
            float4 v1 = p[(2 * i + 2) * 16];
            a0.x += v0.x; a0.y += v0.y; a0.z += v0.z; a0.w += v0.w;
            a1.x += v1.x; a1.y += v1.y; a1.z += v1.z; a1.w += v1.w;
        }
        float4 a;
        a.x = a0.x + a1.x; a.y = a0.y + a1.y; a.z = a0.z + a1.z; a.w = a0.w + a1.w;
        // combine th=0/1 within warp
        a.x += __shfl_xor_sync(0xffffffffu, a.x, 16);
        a.y += __shfl_xor_sync(0xffffffffu, a.y, 16);
        a.z += __shfl_xor_sync(0xffffffffu, a.z, 16);
        a.w += __shfl_xor_sync(0xffffffffu, a.w, 16);

        __shared__ float4 part[4][2][16];
        if (th == 0) part[s_local][wis][f4] = a;
        __syncthreads();

        // combine the two warps of each sample; 64 threads write results
        if (tid < 64) {
            int s  = tid >> 4;
            int f  = tid & 15;
            float4 u = part[s][0][f];
            float4 v = part[s][1][f];
            const float inv = 1.0f / (float)T_;
            float4 r;
            r.x = (u.x + v.x) * inv;
            r.y = (u.y + v.y) * inv;
            r.z = (u.z + v.z) * inv;
            r.w = (u.w + v.w) * inv;
            int so = blockIdx.x * 4 + s;
            dstbase[so * 16 + f] = r;
        }
    } else {
        // ---- gram: block computes G row i; warp w owns j = w*8..w*8+7 ----
        int i    = blockIdx.x - POOLB;
        int warp = tid >> 5;
        int lane = tid & 31;

        float wi[8];
        #pragma unroll
        for (int u = 0; u < 8; u++)
            wi[u] = Wm[i * D_ + lane + 32 * u];

        float s[8];
        #pragma unroll
        for (int jj = 0; jj < 8; jj++) s[jj] = 0.f;

        #pragma unroll
        for (int u = 0; u < 8; u++) {
            #pragma unroll
            for (int jj = 0; jj < 8; jj++)
                s[jj] = fmaf(wi[u], Wm[(warp * 8 + jj) * D_ + lane + 32 * u], s[jj]);
        }

        #pragma unroll
        for (int jj = 0; jj < 8; jj++) {
            #pragma unroll
            for (int off = 16; off > 0; off >>= 1)
                s[jj] += __shfl_xor_sync(0xffffffffu, s[jj], off);
        }
        if (lane == 0) {
            #pragma unroll
            for (int jj = 0; jj < 8; jj++)
                g_G[i * F_ + warp * 8 + jj] = s[jj];
        }
    }
}

// ---------------------------------------------------------------------------
// K2: per-episode prototypes + h_k = G p_k + c_k = p_k.h_k.
// One block per episode, 64 threads (thread = feature f).
// ---------------------------------------------------------------------------
__global__ void __launch_bounds__(64) proto_kernel(const int* __restrict__ y) {
    int b = blockIdx.x;
    int f = threadIdx.x;

    __shared__ int   ys[S_];
    __shared__ float psh[KW][F_];
    __shared__ float csh[KW][F_];

    if (f < S_) ys[f] = y[b * S_ + f];
    __syncthreads();

    float a0=0.f,a1=0.f,a2=0.f,a3=0.f,a4=0.f;
    int   c0=0,c1=0,c2=0,c3=0,c4=0;
    #pragma unroll 10
    for (int s = 0; s < S_; s++) {
        float v = g_spooled[(b * S_ + s) * F_ + f];
        int l = ys[s];
        if (l == 0) { a0 += v; c0++; }
        if (l == 1) { a1 += v; c1++; }
        if (l == 2) { a2 += v; c2++; }
        if (l == 3) { a3 += v; c3++; }
        if (l == 4) { a4 += v; c4++; }
    }
    psh[0][f] = c0 ? a0 / (float)c0 : 0.f;
    psh[1][f] = c1 ? a1 / (float)c1 : 0.f;
    psh[2][f] = c2 ? a2 / (float)c2 : 0.f;
    psh[3][f] = c3 ? a3 / (float)c3 : 0.f;
    psh[4][f] = c4 ? a4 / (float)c4 : 0.f;
    __syncthreads();

    // h[k][f] = sum_i G[i][f] * p[k][i]  (G symmetric -> coalesced reads)
    float hk[KW];
    #pragma unroll
    for (int k = 0; k < KW; k++) hk[k] = 0.f;
    for (int i = 0; i < F_; i++) {
        float gi = g_G[i * F_ + f];
        #pragma unroll
        for (int k = 0; k < KW; k++)
            hk[k] = fmaf(gi, psh[k][i], hk[k]);
    }
    #pragma unroll
    for (int k = 0; k < KW; k++) {
        g_h[(b * KW + k) * F_ + f] = hk[k];
        csh[k][f] = psh[k][f] * hk[k];
    }
    __syncthreads();

    if (f < 32) {
        #pragma unroll
        for (int k = 0; k < KW; k++) {
            float v = csh[k][f] + csh[k][f + 32];
            #pragma unroll
            for (int off = 16; off > 0; off >>= 1)
                v += __shfl_xor_sync(0xffffffffu, v, off);
            if (f == 0) g_c[b * KW + k] = v;
        }
    }
}

// ---------------------------------------------------------------------------
// K3: logits. 300 blocks, warp-per-query. a = q G q^T with G from hot L2
// (no smem staging, no occupancy cliff); five dots vs h_k from L2.
// ---------------------------------------------------------------------------
__global__ void __launch_bounds__(256) dist_kernel(float* __restrict__ out) {
    int tid  = threadIdx.x;
    int warp = tid >> 5;
    int lane = tid & 31;
    int bq   = blockIdx.x * 8 + warp;     // 300*8 = 2400 = NQ exactly
    int b    = bq / Q_;

    __shared__ float qsh[8][F_];

    float q0 = g_qfeat[bq * F_ + lane];
    float q1 = g_qfeat[bq * F_ + lane + 32];
    qsh[warp][lane]      = q0;
    qsh[warp][lane + 32] = q1;
    __syncwarp();

    float e0 = 0.f, e1 = 0.f;
    #pragma unroll
    for (int i = 0; i < F_; i++) {
        float qi = qsh[warp][i];
        e0 = fmaf(g_G[i * F_ + lane],      qi, e0);
        e1 = fmaf(g_G[i * F_ + lane + 32], qi, e1);
    }
    float a = q0 * e0 + q1 * e1;
    #pragma unroll
    for (int off = 16; off > 0; off >>= 1)
        a += __shfl_xor_sync(0xffffffffu, a, off);

    #pragma unroll
    for (int k = 0; k < KW; k++) {
        const float* hk = g_h + (b * KW + k) * F_;
        float s = q0 * hk[lane] + q1 * hk[lane + 32];
        #pragma unroll
        for (int off = 16; off > 0; off >>= 1)
            s += __shfl_xor_sync(0xffffffffu, s, off);
        if (lane == 0)
            out[bq * KW + k] = -sqrtf(fmaxf(a - 2.f * s + g_c[b * KW + k], 0.f));
    }
}

// ---------------------------------------------------------------------------
// Inputs (metadata order): support_x f32, support_y i32, query_x f32, W f32, b f32
// Output: f32 [B*Q, KW] = [2400, 5]
// ---------------------------------------------------------------------------
extern "C" void kernel_launch(void* const* d_in, const int* in_sizes, int n_in,
                              void* d_out, int out_size) {
    const float* sx = (const float*)d_in[0];
    const int*   sy = (const int*)  d_in[1];
    const float* qx = (const float*)d_in[2];
    const float* Wm = (const float*)d_in[3];
    float* out = (float*)d_out;

    poolgram_kernel<<<POOLB + F_, 256>>>(sx, qx, Wm);
    proto_kernel   <<<B_,          64>>>(sy);
    dist_kernel    <<<NQ / 8,     256>>>(out);
}

// round 13
// speedup vs baseline: 1.5210x; 1.2054x over previous
#include <cuda_runtime.h>
#include <math.h>

#define B_  32
#define S_  50
#define Q_  75
#define T_  128
#define F_  64
#define D_  256
#define KW  5
#define NS  (B_*S_)          // 1600 support samples
#define NQ  (B_*Q_)          // 2400 query samples
#define NTOT (NS+NQ)         // 4000
#define POOLB (NTOT/4)       // 1000 pool blocks (4 samples each, 64 thr/sample)

// Scratch (device globals: allocation-free per harness rules)
__device__ float g_spooled[NS * F_];     // pooled support (400 KB, L2-hot)
__device__ float g_qfeat[NQ * F_];       // pooled queries (600 KB)
__device__ float g_G[F_ * F_];           // Gram G = W W^T (16 KB, L2-resident)

// ---------------------------------------------------------------------------
// K1: pool + gram in ONE launch.
//  blocks [0, POOLB): mean-pool, 64 threads/sample, T split 4 ways.
//    4 independent float4 accumulators + unroll -> up to 16 loads in flight
//    per thread (R12 measured DRAM 67% @ regs=32 ~4 in flight; this targets
//    deeper MLP at modest reg cost).
//  blocks [POOLB, POOLB+64): Gram row i (latency-bound, hides under pool).
// ---------------------------------------------------------------------------
__global__ void __launch_bounds__(256) poolgram_kernel(const float* __restrict__ sx,
                                                       const float* __restrict__ qx,
                                                       const float* __restrict__ Wm) {
    int tid = threadIdx.x;

    if (blockIdx.x < POOLB) {
        int lane    = tid & 31;
        int s_local = tid >> 6;          // 0..3
        int wis     = (tid >> 5) & 1;    // warp-in-sample
        int th      = lane >> 4;         // 0..1
        int f4      = lane & 15;         // 0..15

        int sn = blockIdx.x * 4 + s_local;
        const float4* src;
        float4* dstbase;
        if (sn < NS) {
            src     = reinterpret_cast<const float4*>(sx) + (size_t)sn * (T_ * F_ / 4);
            dstbase = reinterpret_cast<float4*>(g_spooled);
        } else {
            src     = reinterpret_cast<const float4*>(qx) + (size_t)(sn - NS) * (T_ * F_ / 4);
            dstbase = reinterpret_cast<float4*>(g_qfeat) - (size_t)NS * 16;
        }

        // t = wis*64 + th + 2*i, i = 0..31. Warp iteration reads 512B contig.
        const float4* p = src + (wis * 64 + th) * 16 + f4;
        float4 a0 = make_float4(0.f,0.f,0.f,0.f);
        float4 a1 = make_float4(0.f,0.f,0.f,0.f);
        float4 a2 = make_float4(0.f,0.f,0.f,0.f);
        float4 a3 = make_float4(0.f,0.f,0.f,0.f);
        #pragma unroll 4
        for (int i = 0; i < 32; i += 4) {
            float4 v0 = p[(2 * i)     * 16];
            float4 v1 = p[(2 * i + 2) * 16];
            float4 v2 = p[(2 * i + 4) * 16];
            float4 v3 = p[(2 * i + 6) * 16];
            a0.x += v0.x; a0.y += v0.y; a0.z += v0.z; a0.w += v0.w;
            a1.x += v1.x; a1.y += v1.y; a1.z += v1.z; a1.w += v1.w;
            a2.x += v2.x; a2.y += v2.y; a2.z += v2.z; a2.w += v2.w;
            a3.x += v3.x; a3.y += v3.y; a3.z += v3.z; a3.w += v3.w;
        }
        float4 a;
        a.x = (a0.x + a1.x) + (a2.x + a3.x);
        a.y = (a0.y + a1.y) + (a2.y + a3.y);
        a.z = (a0.z + a1.z) + (a2.z + a3.z);
        a.w = (a0.w + a1.w) + (a2.w + a3.w);
        a.x += __shfl_xor_sync(0xffffffffu, a.x, 16);
        a.y += __shfl_xor_sync(0xffffffffu, a.y, 16);
        a.z += __shfl_xor_sync(0xffffffffu, a.z, 16);
        a.w += __shfl_xor_sync(0xffffffffu, a.w, 16);

        __shared__ float4 part[4][2][16];
        if (th == 0) part[s_local][wis][f4] = a;
        __syncthreads();

        if (tid < 64) {
            int s = tid >> 4;
            int f = tid & 15;
            float4 u = part[s][0][f];
            float4 v = part[s][1][f];
            const float inv = 1.0f / (float)T_;
            float4 r;
            r.x = (u.x + v.x) * inv;
            r.y = (u.y + v.y) * inv;
            r.z = (u.z + v.z) * inv;
            r.w = (u.w + v.w) * inv;
            dstbase[(blockIdx.x * 4 + s) * 16 + f] = r;
        }
    } else {
        // ---- gram: block computes G row i; warp w owns j = w*8..w*8+7 ----
        int i    = blockIdx.x - POOLB;
        int warp = tid >> 5;
        int lane = tid & 31;

        float wi[8];
        #pragma unroll
        for (int u = 0; u < 8; u++)
            wi[u] = Wm[i * D_ + lane + 32 * u];

        float s[8];
        #pragma unroll
        for (int jj = 0; jj < 8; jj++) s[jj] = 0.f;

        #pragma unroll
        for (int u = 0; u < 8; u++) {
            #pragma unroll
            for (int jj = 0; jj < 8; jj++)
                s[jj] = fmaf(wi[u], Wm[(warp * 8 + jj) * D_ + lane + 32 * u], s[jj]);
        }

        #pragma unroll
        for (int jj = 0; jj < 8; jj++) {
            #pragma unroll
            for (int off = 16; off > 0; off >>= 1)
                s[jj] += __shfl_xor_sync(0xffffffffu, s[jj], off);
        }
        if (lane == 0) {
            #pragma unroll
            for (int jj = 0; jj < 8; jj++)
                g_G[i * F_ + warp * 8 + jj] = s[jj];
        }
    }
}

// ---------------------------------------------------------------------------
// K2: fused proto + dist. 320 blocks = 32 episodes x 10; block handles 8
// queries of episode b = bid/10 and REDUNDANTLY recomputes that episode's
// prototypes/h/c (L2-hot inputs, parallel across blocks -> ~free wall time).
//   phase A: stage G (16 KB) to smem; labels; support partial sums (4 s-groups).
//   phase B: p_k, h_k = G p_k, c_k = p_k.h_k   (64 threads, smem G).
//   phase C: warp-per-query: a = qGq (smem G), s_k = q.h_k, logit.
// ---------------------------------------------------------------------------
__global__ void __launch_bounds__(256) epdist_kernel(const int* __restrict__ y,
                                                     float* __restrict__ out) {
    int tid  = threadIdx.x;
    int lane = tid & 31;
    int warp = tid >> 5;
    int b    = blockIdx.x / 10;
    int r    = blockIdx.x % 10;

    __shared__ float Gs[F_ * F_];        // 16 KB
    __shared__ int   ys[S_];
    __shared__ float partp[4][KW][F_];   // 5 KB  per-s-group class partials
    __shared__ int   partc[4][KW];
    __shared__ float psh[KW][F_];
    __shared__ float hsh[KW][F_];
    __shared__ float csh[KW];
    __shared__ float qsh[8][F_];

    // stage G
    {
        const float4* gsrc = reinterpret_cast<const float4*>(g_G);
        float4* gdst = reinterpret_cast<float4*>(Gs);
        #pragma unroll
        for (int u = 0; u < 4; u++) gdst[tid + 256 * u] = gsrc[tid + 256 * u];
    }
    if (tid < S_) ys[tid] = y[b * S_ + tid];
    __syncthreads();

    // phase A: partial class sums; thread = (sg = tid>>6, f = tid&63)
    {
        int sg = tid >> 6;
        int f  = tid & 63;
        int s0 = sg * 13;
        int s1 = s0 + 13 < S_ ? s0 + 13 : S_;
        float a0=0.f,a1=0.f,a2=0.f,a3=0.f,a4=0.f;
        int   c0=0,c1=0,c2=0,c3=0,c4=0;
        #pragma unroll 13
        for (int s = s0; s < s1; s++) {
            float v = g_spooled[(b * S_ + s) * F_ + f];
            int l = ys[s];
            if (l == 0) { a0 += v; c0++; }
            if (l == 1) { a1 += v; c1++; }
            if (l == 2) { a2 += v; c2++; }
            if (l == 3) { a3 += v; c3++; }
            if (l == 4) { a4 += v; c4++; }
        }
        partp[sg][0][f] = a0; partp[sg][1][f] = a1; partp[sg][2][f] = a2;
        partp[sg][3][f] = a3; partp[sg][4][f] = a4;
        if (f == 0) {
            partc[sg][0] = c0; partc[sg][1] = c1; partc[sg][2] = c2;
            partc[sg][3] = c3; partc[sg][4] = c4;
        }
    }
    __syncthreads();

    // phase B: prototypes, h, c (64 threads; f = tid)
    if (tid < F_) {
        int f = tid;
        #pragma unroll
        for (int k = 0; k < KW; k++) {
            float sum = partp[0][k][f] + partp[1][k][f] + partp[2][k][f] + partp[3][k][f];
            int   cnt = partc[0][k] + partc[1][k] + partc[2][k] + partc[3][k];
            psh[k][f] = cnt ? sum / (float)cnt : 0.f;
        }
    }
    __syncthreads();
    if (tid < F_) {
        int f = tid;
        float hk[KW];
        #pragma unroll
        for (int k = 0; k < KW; k++) hk[k] = 0.f;
        #pragma unroll 8
        for (int i = 0; i < F_; i++) {
            float gi = Gs[i * F_ + f];
            #pragma unroll
            for (int k = 0; k < KW; k++)
                hk[k] = fmaf(gi, psh[k][i], hk[k]);
        }
        #pragma unroll
        for (int k = 0; k < KW; k++) hsh[k][f] = hk[k];
    }
    __syncthreads();
    if (tid < 32) {
        #pragma unroll
        for (int k = 0; k < KW; k++) {
            float v = psh[k][tid] * hsh[k][tid] + psh[k][tid + 32] * hsh[k][tid + 32];
            #pragma unroll
            for (int off = 16; off > 0; off >>= 1)
                v += __shfl_xor_sync(0xffffffffu, v, off);
            if (tid == 0) csh[k] = v;
        }
    }
    __syncthreads();

    // phase C: warp-per-query
    int q = r * 8 + warp;
    if (q >= Q_) return;
    int bq = b * Q_ + q;

    float q0 = g_qfeat[bq * F_ + lane];
    float q1 = g_qfeat[bq * F_ + lane + 32];
    qsh[warp][lane]      = q0;
    qsh[warp][lane + 32] = q1;
    __syncwarp();

    float e0 = 0.f, e1 = 0.f;
    #pragma unroll
    for (int i = 0; i < F_; i++) {
        float qi = qsh[warp][i];
        e0 = fmaf(Gs[i * F_ + lane],      qi, e0);
        e1 = fmaf(Gs[i * F_ + lane + 32], qi, e1);
    }
    float a = q0 * e0 + q1 * e1;
    #pragma unroll
    for (int off = 16; off > 0; off >>= 1)
        a += __shfl_xor_sync(0xffffffffu, a, off);

    #pragma unroll
    for (int k = 0; k < KW; k++) {
        float s = q0 * hsh[k][lane] + q1 * hsh[k][lane + 32];
        #pragma unroll
        for (int off = 16; off > 0; off >>= 1)
            s += __shfl_xor_sync(0xffffffffu, s, off);
        if (lane == 0)
            out[bq * KW + k] = -sqrtf(fmaxf(a - 2.f * s + csh[k], 0.f));
    }
}

// ---------------------------------------------------------------------------
// Inputs (metadata order): support_x f32, support_y i32, query_x f32, W f32, b f32
// Output: f32 [B*Q, KW] = [2400, 5]
// ---------------------------------------------------------------------------
extern "C" void kernel_launch(void* const* d_in, const int* in_sizes, int n_in,
                              void* d_out, int out_size) {
    const float* sx = (const float*)d_in[0];
    const int*   sy = (const int*)  d_in[1];
    const float* qx = (const float*)d_in[2];
    const float* Wm = (const float*)d_in[3];
    float* out = (float*)d_out;

    poolgram_kernel<<<POOLB + F_, 256>>>(sx, qx, Wm);
    epdist_kernel  <<<B_ * 10,    256>>>(sy, out);
}